// round 2
// baseline (speedup 1.0000x reference)
#include <cuda_runtime.h>

#define N_B 16
#define DIM 1024
#define TILE 128

// Scratch (device globals: allocation-free per harness rules)
__device__ float g_a2p[(size_t)N_B * DIM * DIM];   // 64 MB
__device__ float g_S[(size_t)N_B * DIM * DIM];     // 64 MB
__device__ float g_rmax[N_B * DIM];
__device__ float g_rinv[N_B * DIM];
__device__ float g_cmax[N_B * DIM];
__device__ float g_cinv[N_B * DIM];
__device__ float g_cpm[N_B * 4 * DIM];
__device__ float g_cps[N_B * 4 * DIM];

// ---------------------------------------------------------------------------
// NT GEMM: C[m,n] = sum_k A[m,k]*B[n,k] (+bias[n]); inner dim = DIM (1024)
// 128x128 tile, BK=8, 8x8 per thread, 256 threads.
// ---------------------------------------------------------------------------
__global__ __launch_bounds__(256, 2)
void gemm_nt_kernel(const float* __restrict__ Ab, const float* __restrict__ Bb,
                    const float* __restrict__ bias, float* __restrict__ Cb,
                    size_t sA, size_t sB, size_t sC)
{
    const float* A = Ab + blockIdx.z * sA;
    const float* B = Bb + blockIdx.z * sB;
    float* C = Cb + blockIdx.z * sC;

    __shared__ float As[8][TILE];
    __shared__ float Bs[8][TILE];

    const int tid  = threadIdx.x;
    const int tx   = tid & 15;
    const int ty   = tid >> 4;
    const int lrow = tid >> 1;         // 0..127
    const int lcol = (tid & 1) << 2;   // 0 or 4

    const float* Ap = A + (size_t)(blockIdx.y * TILE + lrow) * DIM + lcol;
    const float* Bp = B + (size_t)(blockIdx.x * TILE + lrow) * DIM + lcol;

    float acc[8][8] = {};

    float4 av = *(const float4*)Ap;
    float4 bv = *(const float4*)Bp;

    for (int k0 = 0; k0 < DIM; k0 += 8) {
        __syncthreads();
        As[lcol + 0][lrow] = av.x; As[lcol + 1][lrow] = av.y;
        As[lcol + 2][lrow] = av.z; As[lcol + 3][lrow] = av.w;
        Bs[lcol + 0][lrow] = bv.x; Bs[lcol + 1][lrow] = bv.y;
        Bs[lcol + 2][lrow] = bv.z; Bs[lcol + 3][lrow] = bv.w;
        __syncthreads();
        if (k0 + 8 < DIM) {
            av = *(const float4*)(Ap + k0 + 8);
            bv = *(const float4*)(Bp + k0 + 8);
        }
        #pragma unroll
        for (int kk = 0; kk < 8; kk++) {
            float4 a0 = *(const float4*)&As[kk][ty << 3];
            float4 a1 = *(const float4*)&As[kk][(ty << 3) + 4];
            float4 b0 = *(const float4*)&Bs[kk][tx << 3];
            float4 b1 = *(const float4*)&Bs[kk][(tx << 3) + 4];
            float ra[8] = {a0.x, a0.y, a0.z, a0.w, a1.x, a1.y, a1.z, a1.w};
            float rb[8] = {b0.x, b0.y, b0.z, b0.w, b1.x, b1.y, b1.z, b1.w};
            #pragma unroll
            for (int i = 0; i < 8; i++)
                #pragma unroll
                for (int j = 0; j < 8; j++)
                    acc[i][j] = fmaf(ra[i], rb[j], acc[i][j]);
        }
    }

    const int crow = blockIdx.y * TILE + (ty << 3);
    const int ccol = blockIdx.x * TILE + (tx << 3);
    float bl[8] = {};
    if (bias) {
        float4 q0 = *(const float4*)(bias + ccol);
        float4 q1 = *(const float4*)(bias + ccol + 4);
        bl[0] = q0.x; bl[1] = q0.y; bl[2] = q0.z; bl[3] = q0.w;
        bl[4] = q1.x; bl[5] = q1.y; bl[6] = q1.z; bl[7] = q1.w;
    }
    #pragma unroll
    for (int i = 0; i < 8; i++) {
        float4 o0 = make_float4(acc[i][0] + bl[0], acc[i][1] + bl[1],
                                acc[i][2] + bl[2], acc[i][3] + bl[3]);
        float4 o1 = make_float4(acc[i][4] + bl[4], acc[i][5] + bl[5],
                                acc[i][6] + bl[6], acc[i][7] + bl[7]);
        *(float4*)(C + (size_t)(crow + i) * DIM + ccol)     = o0;
        *(float4*)(C + (size_t)(crow + i) * DIM + ccol + 4) = o1;
    }
}

// ---------------------------------------------------------------------------
// Row softmax stats over k (contiguous): one block per (n,l) row.
// ---------------------------------------------------------------------------
__global__ __launch_bounds__(256)
void row_stats_kernel(const float* __restrict__ S,
                      float* __restrict__ rmax, float* __restrict__ rinv)
{
    const int row = blockIdx.x;
    const float4* p = (const float4*)(S + (size_t)row * DIM);
    const int tid = threadIdx.x;
    float4 v = p[tid];
    float m = fmaxf(fmaxf(v.x, v.y), fmaxf(v.z, v.w));
    __shared__ float red[256];
    red[tid] = m; __syncthreads();
    for (int s = 128; s > 0; s >>= 1) {
        if (tid < s) red[tid] = fmaxf(red[tid], red[tid + s]);
        __syncthreads();
    }
    const float rm = red[0];
    __syncthreads();
    float se = __expf(v.x - rm) + __expf(v.y - rm) + __expf(v.z - rm) + __expf(v.w - rm);
    red[tid] = se; __syncthreads();
    for (int s = 128; s > 0; s >>= 1) {
        if (tid < s) red[tid] += red[tid + s];
        __syncthreads();
    }
    if (tid == 0) { rmax[row] = rm; rinv[row] = 1.0f / red[0]; }
}

// ---------------------------------------------------------------------------
// Column softmax stats over l (strided): partials over 256-row chunks,
// coalesced reads (adjacent threads -> adjacent k), then combine.
// ---------------------------------------------------------------------------
__global__ __launch_bounds__(256)
void col_partial_kernel(const float* __restrict__ S,
                        float* __restrict__ pmax, float* __restrict__ psum)
{
    const int n = blockIdx.z, kc = blockIdx.x, lc = blockIdx.y;
    const int k = kc * 256 + threadIdx.x;
    const float* p = S + ((size_t)n * DIM + lc * 256) * DIM + k;

    float m[8];
    #pragma unroll
    for (int j = 0; j < 8; j++) m[j] = -1e30f;
    for (int l = 0; l < 256; l += 8) {
        #pragma unroll
        for (int j = 0; j < 8; j++) m[j] = fmaxf(m[j], p[(size_t)(l + j) * DIM]);
    }
    float mm = m[0];
    #pragma unroll
    for (int j = 1; j < 8; j++) mm = fmaxf(mm, m[j]);

    float s[8] = {};
    for (int l = 0; l < 256; l += 8) {
        #pragma unroll
        for (int j = 0; j < 8; j++) s[j] += __expf(p[(size_t)(l + j) * DIM] - mm);
    }
    float ss = 0.f;
    #pragma unroll
    for (int j = 0; j < 8; j++) ss += s[j];

    pmax[((size_t)(n * 4 + lc)) * DIM + k] = mm;
    psum[((size_t)(n * 4 + lc)) * DIM + k] = ss;
}

__global__ __launch_bounds__(256)
void col_combine_kernel(const float* __restrict__ pmax, const float* __restrict__ psum,
                        float* __restrict__ cmax, float* __restrict__ cinv)
{
    const int idx = blockIdx.x * 256 + threadIdx.x;   // n*1024 + k
    const int n = idx >> 10, k = idx & 1023;
    float m = -1e30f;
    #pragma unroll
    for (int lc = 0; lc < 4; lc++)
        m = fmaxf(m, pmax[((size_t)(n * 4 + lc)) * DIM + k]);
    float s = 0.f;
    #pragma unroll
    for (int lc = 0; lc < 4; lc++)
        s += psum[((size_t)(n * 4 + lc)) * DIM + k] *
             __expf(pmax[((size_t)(n * 4 + lc)) * DIM + k] - m);
    cmax[idx] = m;
    cinv[idx] = 1.0f / s;
}

// ---------------------------------------------------------------------------
// M1 = rowsoftmax(S) @ a2 : NN GEMM, A-tile transformed on load.
// ---------------------------------------------------------------------------
__global__ __launch_bounds__(256, 2)
void gemm_m1_kernel(const float* __restrict__ Sb, const float* __restrict__ A2b,
                    const float* __restrict__ rmax, const float* __restrict__ rinv,
                    float* __restrict__ Ob)
{
    const int n = blockIdx.z;
    const float* S = Sb + (size_t)n * DIM * DIM;
    const float* B = A2b + (size_t)n * DIM * DIM;
    float* C = Ob + (size_t)n * DIM * DIM;

    __shared__ float As[8][TILE];
    __shared__ float Bs[8][TILE];

    const int tid = threadIdx.x;
    const int tx = tid & 15, ty = tid >> 4;
    const int arow = tid >> 1;
    const int acol = (tid & 1) << 2;
    const int rglob = blockIdx.y * TILE + arow;
    const float rm = rmax[n * DIM + rglob];
    const float ri = rinv[n * DIM + rglob];
    const float* Ap = S + (size_t)rglob * DIM + acol;

    const int brow = tid >> 5;            // 0..7
    const int bcol = (tid & 31) << 2;     // 0..124
    const float* Bp = B + (size_t)brow * DIM + blockIdx.x * TILE + bcol;

    float acc[8][8] = {};
    float4 av = *(const float4*)Ap;
    float4 bv = *(const float4*)Bp;

    for (int k0 = 0; k0 < DIM; k0 += 8) {
        __syncthreads();
        As[acol + 0][arow] = __expf(av.x - rm) * ri;
        As[acol + 1][arow] = __expf(av.y - rm) * ri;
        As[acol + 2][arow] = __expf(av.z - rm) * ri;
        As[acol + 3][arow] = __expf(av.w - rm) * ri;
        *(float4*)&Bs[brow][bcol] = bv;
        __syncthreads();
        if (k0 + 8 < DIM) {
            av = *(const float4*)(Ap + k0 + 8);
            bv = *(const float4*)(Bp + (size_t)(k0 + 8) * DIM);
        }
        #pragma unroll
        for (int kk = 0; kk < 8; kk++) {
            float4 a0 = *(const float4*)&As[kk][ty << 3];
            float4 a1 = *(const float4*)&As[kk][(ty << 3) + 4];
            float4 b0 = *(const float4*)&Bs[kk][tx << 3];
            float4 b1 = *(const float4*)&Bs[kk][(tx << 3) + 4];
            float ra[8] = {a0.x, a0.y, a0.z, a0.w, a1.x, a1.y, a1.z, a1.w};
            float rb[8] = {b0.x, b0.y, b0.z, b0.w, b1.x, b1.y, b1.z, b1.w};
            #pragma unroll
            for (int i = 0; i < 8; i++)
                #pragma unroll
                for (int j = 0; j < 8; j++)
                    acc[i][j] = fmaf(ra[i], rb[j], acc[i][j]);
        }
    }

    const int crow = blockIdx.y * TILE + (ty << 3);
    const int ccol = blockIdx.x * TILE + (tx << 3);
    #pragma unroll
    for (int i = 0; i < 8; i++) {
        float4 o0 = make_float4(acc[i][0], acc[i][1], acc[i][2], acc[i][3]);
        float4 o1 = make_float4(acc[i][4], acc[i][5], acc[i][6], acc[i][7]);
        *(float4*)(C + (size_t)(crow + i) * DIM + ccol)     = o0;
        *(float4*)(C + (size_t)(crow + i) * DIM + ccol + 4) = o1;
    }
}

// ---------------------------------------------------------------------------
// M2 = colsoftmax(S)^T @ a1 : NN GEMM over inner dim l; A-tile reads S
// transposed-logically (rows l contiguous in k) with column transform.
// ---------------------------------------------------------------------------
__global__ __launch_bounds__(256, 2)
void gemm_m2_kernel(const float* __restrict__ Sb, const float* __restrict__ A1b,
                    const float* __restrict__ cmax, const float* __restrict__ cinv,
                    float* __restrict__ Ob)
{
    const int n = blockIdx.z;
    const float* S = Sb + (size_t)n * DIM * DIM;
    const float* B = A1b + (size_t)n * DIM * DIM;   // a1[n]
    float* C = Ob + (size_t)n * DIM * DIM;

    __shared__ float As[8][TILE];   // [l][k]
    __shared__ float Bs[8][TILE];   // [l][d]

    const int tid = threadIdx.x;
    const int tx = tid & 15, ty = tid >> 4;
    const int lrow = tid >> 5;            // 0..7 (l within chunk)
    const int kcol = (tid & 31) << 2;     // 0..124
    const int kglob = blockIdx.y * TILE + kcol;
    float4 cm = *(const float4*)(cmax + n * DIM + kglob);
    float4 ci = *(const float4*)(cinv + n * DIM + kglob);
    const float* Ap = S + (size_t)lrow * DIM + blockIdx.y * TILE + kcol;
    const float* Bp = B + (size_t)lrow * DIM + blockIdx.x * TILE + kcol;

    float acc[8][8] = {};
    float4 av = *(const float4*)Ap;
    float4 bv = *(const float4*)Bp;

    for (int l0 = 0; l0 < DIM; l0 += 8) {
        __syncthreads();
        *(float4*)&As[lrow][kcol] = make_float4(
            __expf(av.x - cm.x) * ci.x, __expf(av.y - cm.y) * ci.y,
            __expf(av.z - cm.z) * ci.z, __expf(av.w - cm.w) * ci.w);
        *(float4*)&Bs[lrow][kcol] = bv;
        __syncthreads();
        if (l0 + 8 < DIM) {
            av = *(const float4*)(Ap + (size_t)(l0 + 8) * DIM);
            bv = *(const float4*)(Bp + (size_t)(l0 + 8) * DIM);
        }
        #pragma unroll
        for (int kk = 0; kk < 8; kk++) {
            float4 a0 = *(const float4*)&As[kk][ty << 3];
            float4 a1 = *(const float4*)&As[kk][(ty << 3) + 4];
            float4 b0 = *(const float4*)&Bs[kk][tx << 3];
            float4 b1 = *(const float4*)&Bs[kk][(tx << 3) + 4];
            float ra[8] = {a0.x, a0.y, a0.z, a0.w, a1.x, a1.y, a1.z, a1.w};
            float rb[8] = {b0.x, b0.y, b0.z, b0.w, b1.x, b1.y, b1.z, b1.w};
            #pragma unroll
            for (int i = 0; i < 8; i++)
                #pragma unroll
                for (int j = 0; j < 8; j++)
                    acc[i][j] = fmaf(ra[i], rb[j], acc[i][j]);
        }
    }

    const int crow = blockIdx.y * TILE + (ty << 3);   // k
    const int ccol = blockIdx.x * TILE + (tx << 3);   // d
    #pragma unroll
    for (int i = 0; i < 8; i++) {
        float4 o0 = make_float4(acc[i][0], acc[i][1], acc[i][2], acc[i][3]);
        float4 o1 = make_float4(acc[i][4], acc[i][5], acc[i][6], acc[i][7]);
        *(float4*)(C + (size_t)(crow + i) * DIM + ccol)     = o0;
        *(float4*)(C + (size_t)(crow + i) * DIM + ccol + 4) = o1;
    }
}

// ---------------------------------------------------------------------------
extern "C" void kernel_launch(void* const* d_in, const int* in_sizes, int n_in,
                              void* d_out, int out_size)
{
    const float* a1 = (const float*)d_in[0];
    const float* a2 = (const float*)d_in[1];
    const float* Gw = (const float*)d_in[2];
    const float* Gb = (const float*)d_in[3];
    float* M1 = (float*)d_out;
    float* M2 = M1 + (size_t)N_B * DIM * DIM;

    float *a2p, *S, *rmax, *rinv, *cmax, *cinv, *cpm, *cps;
    cudaGetSymbolAddress((void**)&a2p, g_a2p);
    cudaGetSymbolAddress((void**)&S,    g_S);
    cudaGetSymbolAddress((void**)&rmax, g_rmax);
    cudaGetSymbolAddress((void**)&rinv, g_rinv);
    cudaGetSymbolAddress((void**)&cmax, g_cmax);
    cudaGetSymbolAddress((void**)&cinv, g_cinv);
    cudaGetSymbolAddress((void**)&cpm,  g_cpm);
    cudaGetSymbolAddress((void**)&cps,  g_cps);

    const size_t mat = (size_t)DIM * DIM;

    // 1) a2p = a2 @ Gw^T + Gb   (rows = N*K = 16384)
    gemm_nt_kernel<<<dim3(8, 128, 1), 256>>>(a2, Gw, Gb, a2p, 0, 0, 0);
    // 2) S[n] = a1[n] @ a2p[n]^T
    gemm_nt_kernel<<<dim3(8, 8, N_B), 256>>>(a1, a2p, nullptr, S, mat, mat, mat);
    // 3) row stats (softmax over k)
    row_stats_kernel<<<N_B * DIM, 256>>>(S, rmax, rinv);
    // 4) col stats (softmax over l)
    col_partial_kernel<<<dim3(4, 4, N_B), 256>>>(S, cpm, cps);
    col_combine_kernel<<<64, 256>>>(cpm, cps, cmax, cinv);
    // 5) M1 = A1 @ a2
    gemm_m1_kernel<<<dim3(8, 8, N_B), 256>>>(S, a2, rmax, rinv, M1);
    // 6) M2 = A2^T @ a1
    gemm_m2_kernel<<<dim3(8, 8, N_B), 256>>>(S, a1, cmax, cinv, M2);
}

// round 4
// speedup vs baseline: 2.8160x; 2.8160x over previous
#include <cuda_runtime.h>
#include <cuda_bf16.h>

#define DIMN 1024
#define NB 16
#define MATS ((size_t)DIMN * DIMN)     /* 1M  */
#define TOT  ((size_t)NB * MATS)       /* 16M */

// ---------------- scratch (device globals; allocation-free) ----------------
__device__ __nv_bfloat16 g_a1h[TOT],  g_a1l[TOT];
__device__ __nv_bfloat16 g_a2h[TOT],  g_a2l[TOT];
__device__ __nv_bfloat16 g_gwh[MATS], g_gwl[MATS];
__device__ __nv_bfloat16 g_a2ph[TOT], g_a2pl[TOT];
__device__ float         g_S[TOT];
__device__ __nv_bfloat16 g_A1h[TOT],  g_A1l[TOT];     // rowsoftmax(S) split
__device__ __nv_bfloat16 g_A2h[TOT],  g_A2l[TOT];     // colsoftmax(S)^T split
__device__ __nv_bfloat16 g_a2Th[TOT], g_a2Tl[TOT];    // a2^T split (per batch)
__device__ __nv_bfloat16 g_a1Th[TOT], g_a1Tl[TOT];    // a1^T split (per batch)
__device__ float g_rmax[NB * DIMN], g_rinv[NB * DIMN];
__device__ float g_cmax[NB * DIMN], g_cinv[NB * DIMN];
__device__ float g_cpm[NB * 8 * DIMN], g_cps[NB * 8 * DIMN];

// ---------------- helpers ----------------
__device__ __forceinline__ unsigned smem_u32(const void* p) {
    unsigned r;
    asm("{ .reg .u64 t; cvta.to.shared.u64 t, %1; cvt.u32.u64 %0, t; }"
        : "=r"(r) : "l"(p));
    return r;
}
// SW64 swizzle for 64-byte rows (8 rows x 64B atom; conflict-free ldmatrix)
__device__ __forceinline__ unsigned swz64(unsigned x) {
    return x ^ ((x >> 3) & 0x30);
}

__device__ __forceinline__ void bsplit(float v, __nv_bfloat16& h, __nv_bfloat16& l) {
    h = __float2bfloat16_rn(v);
    l = __float2bfloat16_rn(v - __bfloat162float(h));
}

#define CP16(dst, src) \
    asm volatile("cp.async.cg.shared.global [%0], [%1], 16;" :: "r"(dst), "l"(src))

#define LDSM4(r, addr) \
    asm volatile("ldmatrix.sync.aligned.m8n8.x4.shared.b16 {%0,%1,%2,%3}, [%4];" \
        : "=r"((r)[0]), "=r"((r)[1]), "=r"((r)[2]), "=r"((r)[3]) : "r"(addr))

#define MMA16816(c, a, b)                                                      \
    asm volatile("mma.sync.aligned.m16n8k16.row.col.f32.bf16.bf16.f32 "        \
        "{%0,%1,%2,%3}, {%4,%5,%6,%7}, {%8,%9}, {%0,%1,%2,%3};"                \
        : "+f"((c)[0]), "+f"((c)[1]), "+f"((c)[2]), "+f"((c)[3])               \
        : "r"((a)[0]), "r"((a)[1]), "r"((a)[2]), "r"((a)[3]),                  \
          "r"((b)[0]), "r"((b)[1]))

// ---------------- split-bf16 NT GEMM via mma.sync ----------------
// C[m,n] = sum_k (Ah+Al)[m,k]*(Bh+Bl)[n,k]   (3-term split, fp32 accum)
// CTA tile 128x128, BK=32, 2-stage cp.async. 256 thr, 8 warps (2x4), warp 64x32.
#define STAGE_B   32768
#define SMEM_TOT  (2 * STAGE_B)

struct GPtr { const char *ah, *al, *bh, *bl; };

__device__ __forceinline__ void issue_loads(unsigned st, const GPtr& p, unsigned kbyte,
                                            unsigned so0, unsigned so1) {
    const unsigned RS = 64u * DIMN * 2u;   // 64-row source step
    CP16(st +     0 + so0, p.ah + kbyte);
    CP16(st +     0 + so1, p.ah + kbyte + RS);
    CP16(st +  8192 + so0, p.al + kbyte);
    CP16(st +  8192 + so1, p.al + kbyte + RS);
    CP16(st + 16384 + so0, p.bh + kbyte);
    CP16(st + 16384 + so1, p.bh + kbyte + RS);
    CP16(st + 24576 + so0, p.bl + kbyte);
    CP16(st + 24576 + so1, p.bl + kbyte + RS);
    asm volatile("cp.async.commit_group;" ::: "memory");
}

// EPI: 0 = fp32 C, 1 = bias add + split bf16 pair out
template <int EPI>
__global__ __launch_bounds__(256, 2)
void gemm_mma(const __nv_bfloat16* __restrict__ Ah, const __nv_bfloat16* __restrict__ Al,
              const __nv_bfloat16* __restrict__ Bh, const __nv_bfloat16* __restrict__ Bl,
              size_t sA, size_t sB, size_t sC,
              float* __restrict__ outF, __nv_bfloat16* __restrict__ outH,
              __nv_bfloat16* __restrict__ outL, const float* __restrict__ bias)
{
    extern __shared__ char smem[];
    const unsigned sb = smem_u32(smem);
    const int tid  = threadIdx.x;
    const int warp = tid >> 5, lane = tid & 31;
    const int wm = (warp >> 2) * 64;      // warp m-offset (0/64)
    const int wn = (warp & 3) * 32;       // warp n-offset (0/32/64/96)

    const size_t z    = blockIdx.z;
    const size_t row0 = (size_t)blockIdx.y * 128;
    const size_t col0 = (size_t)blockIdx.x * 128;

    // cp.async: each thread owns chunk c0=tid and c1=tid+256 of each 8KB subtile.
    // chunk c: row=c>>2 (0..63 for c0), kseg=(c&3)*16 bytes
    GPtr p;
    {
        size_t ar = row0 + (tid >> 2);
        size_t br = col0 + (tid >> 2);
        size_t ko = (size_t)(tid & 3) * 8;  // elems
        p.ah = (const char*)Ah + (z * sA + ar * DIMN + ko) * 2;
        p.al = (const char*)Al + (z * sA + ar * DIMN + ko) * 2;
        p.bh = (const char*)Bh + (z * sB + br * DIMN + ko) * 2;
        p.bl = (const char*)Bl + (z * sB + br * DIMN + ko) * 2;
    }
    const unsigned so0 = swz64(((unsigned)(tid >> 2)) * 64 + (tid & 3) * 16);
    const unsigned so1 = so0 + 4096;      // +64 rows (swizzle bits unchanged)

    float acc[4][4][4] = {};

    issue_loads(sb,           p, 0,  so0, so1);
    issue_loads(sb + STAGE_B, p, 64, so0, so1);

#pragma unroll 1
    for (int it = 0; it < 32; it++) {
        const int s = it & 1;
        const unsigned st = sb + s * STAGE_B;
        if (it < 31) asm volatile("cp.async.wait_group 1;" ::: "memory");
        else         asm volatile("cp.async.wait_group 0;" ::: "memory");
        __syncthreads();

#pragma unroll
        for (int ks = 0; ks < 2; ks++) {
            const unsigned kb = ks * 32;
            // B fragments: 4 n8-frags (h and l)
            unsigned bh[8], bl[8];
#pragma unroll
            for (int nt = 0; nt < 2; nt++) {
                unsigned brow = wn + nt * 16 + (lane & 7) + ((lane >> 4) & 1) * 8;
                unsigned bb   = kb + ((lane >> 3) & 1) * 16;
                unsigned ba   = st + 16384 + swz64(brow * 64 + bb);
                LDSM4(bh + nt * 4, ba);
                LDSM4(bl + nt * 4, ba + 8192);
            }
#pragma unroll
            for (int mf = 0; mf < 4; mf++) {
                unsigned arow = wm + mf * 16 + (lane & 15);
                unsigned ab   = kb + ((lane >> 4) & 1) * 16;
                unsigned aa   = st + swz64(arow * 64 + ab);
                unsigned ah[4], al[4];
                LDSM4(ah, aa);
                LDSM4(al, aa + 8192);
#pragma unroll
                for (int nf = 0; nf < 4; nf++) {
                    MMA16816(acc[mf][nf], ah, bh + nf * 2);   // hi*hi
                    MMA16816(acc[mf][nf], ah, bl + nf * 2);   // hi*lo
                    MMA16816(acc[mf][nf], al, bh + nf * 2);   // lo*hi
                }
            }
        }
        __syncthreads();
        if (it + 2 < 32) issue_loads(st, p, (unsigned)(it + 2) * 64, so0, so1);
    }

    // ---- epilogue: accumulators -> global ----
    const int g = lane >> 2, t = lane & 3;
#pragma unroll
    for (int mf = 0; mf < 4; mf++) {
#pragma unroll
        for (int nf = 0; nf < 4; nf++) {
            const float* c = acc[mf][nf];
            size_t r0 = row0 + wm + mf * 16 + g;
            size_t cc = col0 + wn + nf * 8 + 2 * t;
            if (EPI == 1) {
                float b0 = bias[cc], b1 = bias[cc + 1];
                union { __nv_bfloat16 b[2]; unsigned u; } H0, L0, H1, L1;
                bsplit(c[0] + b0, H0.b[0], L0.b[0]);
                bsplit(c[1] + b1, H0.b[1], L0.b[1]);
                bsplit(c[2] + b0, H1.b[0], L1.b[0]);
                bsplit(c[3] + b1, H1.b[1], L1.b[1]);
                *(unsigned*)(outH + r0 * DIMN + cc)       = H0.u;
                *(unsigned*)(outL + r0 * DIMN + cc)       = L0.u;
                *(unsigned*)(outH + (r0 + 8) * DIMN + cc) = H1.u;
                *(unsigned*)(outL + (r0 + 8) * DIMN + cc) = L1.u;
            } else {
                float* o = outF + z * sC;
                *(float2*)(o + r0 * DIMN + cc)       = make_float2(c[0], c[1]);
                *(float2*)(o + (r0 + 8) * DIMN + cc) = make_float2(c[2], c[3]);
            }
        }
    }
}

// ---------------- elementwise / stats ----------------
__global__ __launch_bounds__(256)
void split_kernel(const float* __restrict__ in, __nv_bfloat16* __restrict__ h,
                  __nv_bfloat16* __restrict__ l)
{
    size_t i = (size_t)blockIdx.x * 256 + threadIdx.x;   // float4 units
    float4 v = ((const float4*)in)[i];
    union { __nv_bfloat16 b[4]; uint2 u; } H, L;
    bsplit(v.x, H.b[0], L.b[0]); bsplit(v.y, H.b[1], L.b[1]);
    bsplit(v.z, H.b[2], L.b[2]); bsplit(v.w, H.b[3], L.b[3]);
    ((uint2*)h)[i] = H.u;
    ((uint2*)l)[i] = L.u;
}

__global__ __launch_bounds__(256)
void row_stats_kernel(const float* __restrict__ S,
                      float* __restrict__ rmax, float* __restrict__ rinv)
{
    const int row = blockIdx.x;
    const float4* p = (const float4*)(S + (size_t)row * DIMN);
    const int tid = threadIdx.x;
    float4 v = p[tid];
    float m = fmaxf(fmaxf(v.x, v.y), fmaxf(v.z, v.w));
    __shared__ float red[256];
    red[tid] = m; __syncthreads();
    for (int s = 128; s > 0; s >>= 1) {
        if (tid < s) red[tid] = fmaxf(red[tid], red[tid + s]);
        __syncthreads();
    }
    const float rm = red[0];
    __syncthreads();
    float se = __expf(v.x - rm) + __expf(v.y - rm) + __expf(v.z - rm) + __expf(v.w - rm);
    red[tid] = se; __syncthreads();
    for (int s = 128; s > 0; s >>= 1) {
        if (tid < s) red[tid] += red[tid + s];
        __syncthreads();
    }
    if (tid == 0) { rmax[row] = rm; rinv[row] = 1.0f / red[0]; }
}

__global__ __launch_bounds__(256)
void col_partial_kernel(const float* __restrict__ S,
                        float* __restrict__ pmax, float* __restrict__ psum)
{
    const int n = blockIdx.z, kc = blockIdx.x, lc = blockIdx.y;
    const int k = kc * 256 + threadIdx.x;
    const float* p = S + ((size_t)n * DIMN + lc * 128) * DIMN + k;
    float m[4] = {-1e30f, -1e30f, -1e30f, -1e30f};
    for (int l0 = 0; l0 < 128; l0 += 4) {
#pragma unroll
        for (int j = 0; j < 4; j++) m[j] = fmaxf(m[j], p[(size_t)(l0 + j) * DIMN]);
    }
    float mm = fmaxf(fmaxf(m[0], m[1]), fmaxf(m[2], m[3]));
    float s[4] = {};
    for (int l0 = 0; l0 < 128; l0 += 4) {
#pragma unroll
        for (int j = 0; j < 4; j++) s[j] += __expf(p[(size_t)(l0 + j) * DIMN] - mm);
    }
    size_t o = ((size_t)(n * 8 + lc)) * DIMN + k;
    pmax[o] = mm;
    psum[o] = s[0] + s[1] + s[2] + s[3];
}

__global__ __launch_bounds__(256)
void col_combine_kernel(const float* __restrict__ pmax, const float* __restrict__ psum,
                        float* __restrict__ cmax, float* __restrict__ cinv)
{
    const int idx = blockIdx.x * 256 + threadIdx.x;   // n*1024 + k
    const int n = idx >> 10, k = idx & 1023;
    float m = -1e30f;
#pragma unroll
    for (int lc = 0; lc < 8; lc++)
        m = fmaxf(m, pmax[((size_t)(n * 8 + lc)) * DIMN + k]);
    float s = 0.f;
#pragma unroll
    for (int lc = 0; lc < 8; lc++)
        s += psum[((size_t)(n * 8 + lc)) * DIMN + k] *
             __expf(pmax[((size_t)(n * 8 + lc)) * DIMN + k] - m);
    cmax[idx] = m;
    cinv[idx] = 1.0f / s;
}

// A1 = exp(S - rmax) * rinv (rowwise), split bf16
__global__ __launch_bounds__(256)
void a1_transform_kernel(const float* __restrict__ S, const float* __restrict__ rmax,
                         const float* __restrict__ rinv,
                         __nv_bfloat16* __restrict__ h, __nv_bfloat16* __restrict__ l)
{
    size_t i = (size_t)blockIdx.x * 256 + threadIdx.x;   // float4 units
    int row = (int)(i >> 8);
    float rm = rmax[row], ri = rinv[row];
    float4 v = ((const float4*)S)[i];
    union { __nv_bfloat16 b[4]; uint2 u; } H, L;
    bsplit(__expf(v.x - rm) * ri, H.b[0], L.b[0]);
    bsplit(__expf(v.y - rm) * ri, H.b[1], L.b[1]);
    bsplit(__expf(v.z - rm) * ri, H.b[2], L.b[2]);
    bsplit(__expf(v.w - rm) * ri, H.b[3], L.b[3]);
    ((uint2*)h)[i] = H.u;
    ((uint2*)l)[i] = L.u;
}

// Transpose (+optional col-softmax transform) + split. in[z][r][c] -> out[z][c][r].
__global__ __launch_bounds__(256)
void tsplit_kernel(const float* __restrict__ in, __nv_bfloat16* __restrict__ h,
                   __nv_bfloat16* __restrict__ l, const float* __restrict__ cmax,
                   const float* __restrict__ cinv)
{
    __shared__ float t[32][33];
    const int z = blockIdx.z;
    const float* src = in + (size_t)z * MATS;
    const int bx = blockIdx.x * 32, by = blockIdx.y * 32;
    const int x = threadIdx.x, y = threadIdx.y;   // block (32, 8)
#pragma unroll
    for (int i = 0; i < 4; i++)
        t[y + 8 * i][x] = src[(size_t)(by + y + 8 * i) * DIMN + bx + x];
    __syncthreads();
#pragma unroll
    for (int i = 0; i < 4; i++) {
        int cI = bx + y + 8 * i;        // output row = input col
        float v = t[x][y + 8 * i];
        if (cmax) v = __expf(v - cmax[z * DIMN + cI]) * cinv[z * DIMN + cI];
        __nv_bfloat16 hh, ll;
        bsplit(v, hh, ll);
        size_t o = (size_t)z * MATS + (size_t)cI * DIMN + by + x;
        h[o] = hh;
        l[o] = ll;
    }
}

// ---------------- launcher ----------------
extern "C" void kernel_launch(void* const* d_in, const int* in_sizes, int n_in,
                              void* d_out, int out_size)
{
    const float* a1 = (const float*)d_in[0];
    const float* a2 = (const float*)d_in[1];
    const float* Gw = (const float*)d_in[2];
    const float* Gb = (const float*)d_in[3];
    float* M1 = (float*)d_out;
    float* M2 = M1 + TOT;

    __nv_bfloat16 *a1h, *a1l, *a2h, *a2l, *gwh, *gwl, *a2ph, *a2pl;
    __nv_bfloat16 *A1h, *A1l, *A2h, *A2l, *a2Th, *a2Tl, *a1Th, *a1Tl;
    float *S, *rmax, *rinv, *cmax, *cinv, *cpm, *cps;
    cudaGetSymbolAddress((void**)&a1h, g_a1h);   cudaGetSymbolAddress((void**)&a1l, g_a1l);
    cudaGetSymbolAddress((void**)&a2h, g_a2h);   cudaGetSymbolAddress((void**)&a2l, g_a2l);
    cudaGetSymbolAddress((void**)&gwh, g_gwh);   cudaGetSymbolAddress((void**)&gwl, g_gwl);
    cudaGetSymbolAddress((void**)&a2ph, g_a2ph); cudaGetSymbolAddress((void**)&a2pl, g_a2pl);
    cudaGetSymbolAddress((void**)&A1h, g_A1h);   cudaGetSymbolAddress((void**)&A1l, g_A1l);
    cudaGetSymbolAddress((void**)&A2h, g_A2h);   cudaGetSymbolAddress((void**)&A2l, g_A2l);
    cudaGetSymbolAddress((void**)&a2Th, g_a2Th); cudaGetSymbolAddress((void**)&a2Tl, g_a2Tl);
    cudaGetSymbolAddress((void**)&a1Th, g_a1Th); cudaGetSymbolAddress((void**)&a1Tl, g_a1Tl);
    cudaGetSymbolAddress((void**)&S, g_S);
    cudaGetSymbolAddress((void**)&rmax, g_rmax); cudaGetSymbolAddress((void**)&rinv, g_rinv);
    cudaGetSymbolAddress((void**)&cmax, g_cmax); cudaGetSymbolAddress((void**)&cinv, g_cinv);
    cudaGetSymbolAddress((void**)&cpm, g_cpm);   cudaGetSymbolAddress((void**)&cps, g_cps);

    cudaFuncSetAttribute(gemm_mma<0>, cudaFuncAttributeMaxDynamicSharedMemorySize, SMEM_TOT);
    cudaFuncSetAttribute(gemm_mma<1>, cudaFuncAttributeMaxDynamicSharedMemorySize, SMEM_TOT);

    // splits
    split_kernel<<<16384, 256>>>(a1, a1h, a1l);
    split_kernel<<<16384, 256>>>(a2, a2h, a2l);
    split_kernel<<<1024, 256>>>(Gw, gwh, gwl);

    // 1) a2p = a2 @ Gw^T + Gb  -> split bf16 pair  (M = 16384, N = 1024)
    gemm_mma<1><<<dim3(8, 128, 1), 256, SMEM_TOT>>>(
        a2h, a2l, gwh, gwl, 0, 0, 0, nullptr, a2ph, a2pl, Gb);

    // 2) S[n] = a1[n] @ a2p[n]^T  -> fp32
    gemm_mma<0><<<dim3(8, 8, NB), 256, SMEM_TOT>>>(
        a1h, a1l, a2ph, a2pl, MATS, MATS, MATS, S, nullptr, nullptr, nullptr);

    // 3) softmax stats
    row_stats_kernel<<<NB * DIMN, 256>>>(S, rmax, rinv);
    col_partial_kernel<<<dim3(4, 8, NB), 256>>>(S, cpm, cps);
    col_combine_kernel<<<64, 256>>>(cpm, cps, cmax, cinv);

    // 4) transforms: A1 (rowwise), A2^T (colwise + transpose)
    a1_transform_kernel<<<16384, 256>>>(S, rmax, rinv, A1h, A1l);
    tsplit_kernel<<<dim3(32, 32, NB), dim3(32, 8)>>>(S, A2h, A2l, cmax, cinv);

    // 5) transposed operand splits
    tsplit_kernel<<<dim3(32, 32, NB), dim3(32, 8)>>>(a2, a2Th, a2Tl, nullptr, nullptr);
    tsplit_kernel<<<dim3(32, 32, NB), dim3(32, 8)>>>(a1, a1Th, a1Tl, nullptr, nullptr);

    // 6) M1 = A1 @ a2  (NT vs a2^T)
    gemm_mma<0><<<dim3(8, 8, NB), 256, SMEM_TOT>>>(
        A1h, A1l, a2Th, a2Tl, MATS, MATS, MATS, M1, nullptr, nullptr, nullptr);

    // 7) M2 = A2^T @ a1  (NT vs a1^T)
    gemm_mma<0><<<dim3(8, 8, NB), 256, SMEM_TOT>>>(
        A2h, A2l, a1Th, a1Tl, MATS, MATS, MATS, M2, nullptr, nullptr, nullptr);
}

// round 5
// speedup vs baseline: 2.9028x; 1.0308x over previous
#include <cuda_runtime.h>
#include <cuda_bf16.h>

#define DIMN 1024
#define NB 16
#define MATS ((size_t)DIMN * DIMN)     /* 1M  */
#define TOT  ((size_t)NB * MATS)       /* 16M */

// ---------------- scratch (device globals; allocation-free) ----------------
__device__ __nv_bfloat16 g_a1h[TOT],  g_a1l[TOT];
__device__ __nv_bfloat16 g_a2h[TOT],  g_a2l[TOT];
__device__ __nv_bfloat16 g_gwh[MATS], g_gwl[MATS];
__device__ __nv_bfloat16 g_a2ph[TOT], g_a2pl[TOT];
__device__ float         g_S[TOT];
__device__ __nv_bfloat16 g_A1h[TOT],  g_A1l[TOT];     // rowsoftmax(S)
__device__ __nv_bfloat16 g_A2h[TOT],  g_A2l[TOT];     // colsoftmax(S)^T
__device__ __nv_bfloat16 g_a2Th[TOT], g_a2Tl[TOT];    // a2^T
__device__ __nv_bfloat16 g_a1Th[TOT], g_a1Tl[TOT];    // a1^T
__device__ float g_rmax[NB * DIMN], g_rinv[NB * DIMN];
__device__ float g_cmax[NB * DIMN], g_cinv[NB * DIMN];
__device__ float g_rpm[NB * 8 * DIMN], g_rps[NB * 8 * DIMN];  // row partials [z][row][bx]
__device__ float g_cpm[NB * 8 * DIMN], g_cps[NB * 8 * DIMN];  // col partials [z][col][by]

// ---------------- helpers ----------------
__device__ __forceinline__ unsigned smem_u32(const void* p) {
    unsigned r;
    asm("{ .reg .u64 t; cvta.to.shared.u64 t, %1; cvt.u32.u64 %0, t; }"
        : "=r"(r) : "l"(p));
    return r;
}
__device__ __forceinline__ unsigned swz64(unsigned x) {
    return x ^ ((x >> 3) & 0x30);
}
__device__ __forceinline__ void bsplit(float v, __nv_bfloat16& h, __nv_bfloat16& l) {
    h = __float2bfloat16_rn(v);
    l = __float2bfloat16_rn(v - __bfloat162float(h));
}

#define CP16(dst, src) \
    asm volatile("cp.async.cg.shared.global [%0], [%1], 16;" :: "r"(dst), "l"(src))

#define LDSM4(r, addr) \
    asm volatile("ldmatrix.sync.aligned.m8n8.x4.shared.b16 {%0,%1,%2,%3}, [%4];" \
        : "=r"((r)[0]), "=r"((r)[1]), "=r"((r)[2]), "=r"((r)[3]) : "r"(addr))

#define MMA16816(c, a, b)                                                      \
    asm volatile("mma.sync.aligned.m16n8k16.row.col.f32.bf16.bf16.f32 "        \
        "{%0,%1,%2,%3}, {%4,%5,%6,%7}, {%8,%9}, {%0,%1,%2,%3};"                \
        : "+f"((c)[0]), "+f"((c)[1]), "+f"((c)[2]), "+f"((c)[3])               \
        : "r"((a)[0]), "r"((a)[1]), "r"((a)[2]), "r"((a)[3]),                  \
          "r"((b)[0]), "r"((b)[1]))

// ---------------- split-bf16 NT GEMM core (mma.sync) ----------------
// C[m,n] = sum_k (Ah+Al)[m,k]*(Bh+Bl)[n,k].  CTA 128x128, BK=32, 3-stage,
// 256 thr, 8 warps (2x4), warp tile 64x32.  One __syncthreads per iter.
#define STAGE_B   32768
#define SMEM_TOT  (3 * STAGE_B)

struct GPtr { const char *ah, *al, *bh, *bl; };

__device__ __forceinline__ void issue_loads(unsigned st, const GPtr& p, unsigned kbyte,
                                            unsigned so0, unsigned so1) {
    const unsigned RS = 64u * DIMN * 2u;
    CP16(st +     0 + so0, p.ah + kbyte);
    CP16(st +     0 + so1, p.ah + kbyte + RS);
    CP16(st +  8192 + so0, p.al + kbyte);
    CP16(st +  8192 + so1, p.al + kbyte + RS);
    CP16(st + 16384 + so0, p.bh + kbyte);
    CP16(st + 16384 + so1, p.bh + kbyte + RS);
    CP16(st + 24576 + so0, p.bl + kbyte);
    CP16(st + 24576 + so1, p.bl + kbyte + RS);
    asm volatile("cp.async.commit_group;" ::: "memory");
}

__device__ __forceinline__ void mainloop(unsigned sb, const GPtr& p,
                                         unsigned so0, unsigned so1,
                                         int lane, int wm, int wn,
                                         float (*acc)[4][4])
{
    issue_loads(sb,           p, 0,  so0, so1);
    issue_loads(sb + STAGE_B, p, 64, so0, so1);

#pragma unroll 1
    for (int it = 0; it < 32; it++) {
        if (it < 31) asm volatile("cp.async.wait_group 1;" ::: "memory");
        else         asm volatile("cp.async.wait_group 0;" ::: "memory");
        __syncthreads();
        if (it + 2 < 32) {
            unsigned wst = sb + (unsigned)((it + 2) % 3) * STAGE_B;
            issue_loads(wst, p, (unsigned)(it + 2) * 64, so0, so1);
        }
        const unsigned st = sb + (unsigned)(it % 3) * STAGE_B;

#pragma unroll
        for (int ks = 0; ks < 2; ks++) {
            const unsigned kb = ks * 32;
            unsigned bh[8], bl[8];
#pragma unroll
            for (int nt = 0; nt < 2; nt++) {
                unsigned brow = wn + nt * 16 + (lane & 7) + ((lane >> 4) & 1) * 8;
                unsigned bb   = kb + ((lane >> 3) & 1) * 16;
                unsigned ba   = st + 16384 + swz64(brow * 64 + bb);
                LDSM4(bh + nt * 4, ba);
                LDSM4(bl + nt * 4, ba + 8192);
            }
#pragma unroll
            for (int mf = 0; mf < 4; mf++) {
                unsigned arow = wm + mf * 16 + (lane & 15);
                unsigned ab   = kb + ((lane >> 4) & 1) * 16;
                unsigned aa   = st + swz64(arow * 64 + ab);
                unsigned ah[4], al[4];
                LDSM4(ah, aa);
                LDSM4(al, aa + 8192);
#pragma unroll
                for (int nf = 0; nf < 4; nf++) {
                    MMA16816(acc[mf][nf], ah, bh + nf * 2);
                    MMA16816(acc[mf][nf], ah, bl + nf * 2);
                    MMA16816(acc[mf][nf], al, bh + nf * 2);
                }
            }
        }
    }
}

__device__ __forceinline__ void make_gptr(GPtr& p, unsigned& so0, unsigned& so1,
    const __nv_bfloat16* Ah, const __nv_bfloat16* Al,
    const __nv_bfloat16* Bh, const __nv_bfloat16* Bl,
    size_t zA, size_t zB, size_t row0, size_t col0, int tid)
{
    size_t ar = row0 + (tid >> 2);
    size_t br = col0 + (tid >> 2);
    size_t ko = (size_t)(tid & 3) * 8;
    p.ah = (const char*)Ah + (zA + ar * DIMN + ko) * 2;
    p.al = (const char*)Al + (zA + ar * DIMN + ko) * 2;
    p.bh = (const char*)Bh + (zB + br * DIMN + ko) * 2;
    p.bl = (const char*)Bl + (zB + br * DIMN + ko) * 2;
    so0 = swz64(((unsigned)(tid >> 2)) * 64 + (tid & 3) * 16);
    so1 = so0 + 4096;
}

// ---- EPI=1: a2p GEMM — bias add + split bf16 pair out (M=16384) ----
__global__ __launch_bounds__(256, 2)
void gemm_a2p(const __nv_bfloat16* __restrict__ Ah, const __nv_bfloat16* __restrict__ Al,
              const __nv_bfloat16* __restrict__ Bh, const __nv_bfloat16* __restrict__ Bl,
              __nv_bfloat16* __restrict__ outH, __nv_bfloat16* __restrict__ outL,
              const float* __restrict__ bias)
{
    extern __shared__ char smem[];
    const unsigned sb = smem_u32(smem);
    const int tid = threadIdx.x, warp = tid >> 5, lane = tid & 31;
    const int wm = (warp >> 2) * 64, wn = (warp & 3) * 32;
    const size_t row0 = (size_t)blockIdx.y * 128, col0 = (size_t)blockIdx.x * 128;

    GPtr p; unsigned so0, so1;
    make_gptr(p, so0, so1, Ah, Al, Bh, Bl, 0, 0, row0, col0, tid);
    float acc[4][4][4] = {};
    mainloop(sb, p, so0, so1, lane, wm, wn, acc);

    const int g = lane >> 2, t = lane & 3;
#pragma unroll
    for (int mf = 0; mf < 4; mf++)
#pragma unroll
        for (int nf = 0; nf < 4; nf++) {
            const float* c = acc[mf][nf];
            size_t r0 = row0 + wm + mf * 16 + g;
            size_t cc = col0 + wn + nf * 8 + 2 * t;
            float b0 = bias[cc], b1 = bias[cc + 1];
            union { __nv_bfloat16 b[2]; unsigned u; } H0, L0, H1, L1;
            bsplit(c[0] + b0, H0.b[0], L0.b[0]);
            bsplit(c[1] + b1, H0.b[1], L0.b[1]);
            bsplit(c[2] + b0, H1.b[0], L1.b[0]);
            bsplit(c[3] + b1, H1.b[1], L1.b[1]);
            *(unsigned*)(outH + r0 * DIMN + cc)       = H0.u;
            *(unsigned*)(outL + r0 * DIMN + cc)       = L0.u;
            *(unsigned*)(outH + (r0 + 8) * DIMN + cc) = H1.u;
            *(unsigned*)(outL + (r0 + 8) * DIMN + cc) = L1.u;
        }
}

// ---- EPI=2: S GEMM — fp32 out + per-CTA row/col softmax partials ----
__global__ __launch_bounds__(256, 2)
void gemm_S(const __nv_bfloat16* __restrict__ Ah, const __nv_bfloat16* __restrict__ Al,
            const __nv_bfloat16* __restrict__ Bh, const __nv_bfloat16* __restrict__ Bl,
            float* __restrict__ outF,
            float* __restrict__ rpm, float* __restrict__ rps,
            float* __restrict__ cpm, float* __restrict__ cps)
{
    extern __shared__ char smem[];
    const unsigned sb = smem_u32(smem);
    const int tid = threadIdx.x, warp = tid >> 5, lane = tid & 31;
    const int wm = (warp >> 2) * 64, wn = (warp & 3) * 32;
    const size_t z = blockIdx.z;
    const size_t row0 = (size_t)blockIdx.y * 128, col0 = (size_t)blockIdx.x * 128;

    GPtr p; unsigned so0, so1;
    make_gptr(p, so0, so1, Ah, Al, Bh, Bl, z * MATS, z * MATS, row0, col0, tid);
    float acc[4][4][4] = {};
    mainloop(sb, p, so0, so1, lane, wm, wn, acc);

    const int g = lane >> 2, t = lane & 3;
    float* outb = outF + z * MATS;
#pragma unroll
    for (int mf = 0; mf < 4; mf++)
#pragma unroll
        for (int nf = 0; nf < 4; nf++) {
            const float* c = acc[mf][nf];
            size_t r0 = row0 + wm + mf * 16 + g;
            size_t cc = col0 + wn + nf * 8 + 2 * t;
            *(float2*)(outb + r0 * DIMN + cc)       = make_float2(c[0], c[1]);
            *(float2*)(outb + (r0 + 8) * DIMN + cc) = make_float2(c[2], c[3]);
        }

    // ---- softmax partials from registers ----
    float rm_[4][2], rs_[4][2];
#pragma unroll
    for (int mf = 0; mf < 4; mf++)
#pragma unroll
        for (int rh = 0; rh < 2; rh++) {
            float m = -1e30f;
#pragma unroll
            for (int nf = 0; nf < 4; nf++)
                m = fmaxf(m, fmaxf(acc[mf][nf][rh * 2], acc[mf][nf][rh * 2 + 1]));
            m = fmaxf(m, __shfl_xor_sync(0xffffffffu, m, 1));
            m = fmaxf(m, __shfl_xor_sync(0xffffffffu, m, 2));
            float s = 0.f;
#pragma unroll
            for (int nf = 0; nf < 4; nf++)
                s += __expf(acc[mf][nf][rh * 2] - m) + __expf(acc[mf][nf][rh * 2 + 1] - m);
            s += __shfl_xor_sync(0xffffffffu, s, 1);
            s += __shfl_xor_sync(0xffffffffu, s, 2);
            rm_[mf][rh] = m; rs_[mf][rh] = s;
        }
    float cm_[4][2], cs_[4][2];
#pragma unroll
    for (int nf = 0; nf < 4; nf++)
#pragma unroll
        for (int cr = 0; cr < 2; cr++) {
            float m = -1e30f;
#pragma unroll
            for (int mf = 0; mf < 4; mf++)
                m = fmaxf(m, fmaxf(acc[mf][nf][cr], acc[mf][nf][2 + cr]));
            m = fmaxf(m, __shfl_xor_sync(0xffffffffu, m, 4));
            m = fmaxf(m, __shfl_xor_sync(0xffffffffu, m, 8));
            m = fmaxf(m, __shfl_xor_sync(0xffffffffu, m, 16));
            float s = 0.f;
#pragma unroll
            for (int mf = 0; mf < 4; mf++)
                s += __expf(acc[mf][nf][cr] - m) + __expf(acc[mf][nf][2 + cr] - m);
            s += __shfl_xor_sync(0xffffffffu, s, 4);
            s += __shfl_xor_sync(0xffffffffu, s, 8);
            s += __shfl_xor_sync(0xffffffffu, s, 16);
            cm_[nf][cr] = m; cs_[nf][cr] = s;
        }

    __syncthreads();   // stage buffers dead; reuse smem for staging
    float* sRM = (float*)smem;        // [4][128]
    float* sRS = sRM + 512;
    float* sCM = sRS + 512;           // [2][128]
    float* sCS = sCM + 256;
    if (t == 0) {
#pragma unroll
        for (int mf = 0; mf < 4; mf++)
#pragma unroll
            for (int rh = 0; rh < 2; rh++) {
                int r = wm + mf * 16 + g + 8 * rh;
                sRM[(warp & 3) * 128 + r] = rm_[mf][rh];
                sRS[(warp & 3) * 128 + r] = rs_[mf][rh];
            }
    }
    if (g == 0) {
#pragma unroll
        for (int nf = 0; nf < 4; nf++)
#pragma unroll
            for (int cr = 0; cr < 2; cr++) {
                int c = wn + nf * 8 + 2 * t + cr;
                sCM[(warp >> 2) * 128 + c] = cm_[nf][cr];
                sCS[(warp >> 2) * 128 + c] = cs_[nf][cr];
            }
    }
    __syncthreads();
    if (tid < 128) {
        int r = tid;
        float m = -1e30f;
#pragma unroll
        for (int w = 0; w < 4; w++) m = fmaxf(m, sRM[w * 128 + r]);
        float s = 0.f;
#pragma unroll
        for (int w = 0; w < 4; w++) s += sRS[w * 128 + r] * __expf(sRM[w * 128 + r] - m);
        size_t ri = (z * DIMN + row0 + r) * 8 + blockIdx.x;
        rpm[ri] = m; rps[ri] = s;

        float mc = fmaxf(sCM[r], sCM[128 + r]);
        float sc = sCS[r] * __expf(sCM[r] - mc) + sCS[128 + r] * __expf(sCM[128 + r] - mc);
        size_t ci = (z * DIMN + col0 + r) * 8 + blockIdx.y;
        cpm[ci] = mc; cps[ci] = sc;
    }
}

// ---- merged M1/M2 GEMM: grid z in [0,32), sel = z>>4 ----
__global__ __launch_bounds__(256, 2)
void gemm_dual(const __nv_bfloat16* __restrict__ A1h, const __nv_bfloat16* __restrict__ A1l,
               const __nv_bfloat16* __restrict__ B1h, const __nv_bfloat16* __restrict__ B1l,
               float* __restrict__ o1,
               const __nv_bfloat16* __restrict__ A2h, const __nv_bfloat16* __restrict__ A2l,
               const __nv_bfloat16* __restrict__ B2h, const __nv_bfloat16* __restrict__ B2l,
               float* __restrict__ o2)
{
    extern __shared__ char smem[];
    const unsigned sb = smem_u32(smem);
    const int tid = threadIdx.x, warp = tid >> 5, lane = tid & 31;
    const int wm = (warp >> 2) * 64, wn = (warp & 3) * 32;
    const int sel = blockIdx.z >> 4;
    const size_t z = blockIdx.z & 15;
    const size_t row0 = (size_t)blockIdx.y * 128, col0 = (size_t)blockIdx.x * 128;

    const __nv_bfloat16* Ah = sel ? A2h : A1h;
    const __nv_bfloat16* Al = sel ? A2l : A1l;
    const __nv_bfloat16* Bh = sel ? B2h : B1h;
    const __nv_bfloat16* Bl = sel ? B2l : B1l;
    float* outF = sel ? o2 : o1;

    GPtr p; unsigned so0, so1;
    make_gptr(p, so0, so1, Ah, Al, Bh, Bl, z * MATS, z * MATS, row0, col0, tid);
    float acc[4][4][4] = {};
    mainloop(sb, p, so0, so1, lane, wm, wn, acc);

    const int g = lane >> 2, t = lane & 3;
    float* outb = outF + z * MATS;
#pragma unroll
    for (int mf = 0; mf < 4; mf++)
#pragma unroll
        for (int nf = 0; nf < 4; nf++) {
            const float* c = acc[mf][nf];
            size_t r0 = row0 + wm + mf * 16 + g;
            size_t cc = col0 + wn + nf * 8 + 2 * t;
            *(float2*)(outb + r0 * DIMN + cc)       = make_float2(c[0], c[1]);
            *(float2*)(outb + (r0 + 8) * DIMN + cc) = make_float2(c[2], c[3]);
        }
}

// ---------------- elementwise / stats ----------------
__global__ __launch_bounds__(256)
void split_kernel(const float* __restrict__ in, __nv_bfloat16* __restrict__ h,
                  __nv_bfloat16* __restrict__ l)
{
    size_t i = (size_t)blockIdx.x * 256 + threadIdx.x;
    float4 v = ((const float4*)in)[i];
    union { __nv_bfloat16 b[4]; uint2 u; } H, L;
    bsplit(v.x, H.b[0], L.b[0]); bsplit(v.y, H.b[1], L.b[1]);
    bsplit(v.z, H.b[2], L.b[2]); bsplit(v.w, H.b[3], L.b[3]);
    ((uint2*)h)[i] = H.u;
    ((uint2*)l)[i] = L.u;
}

// combine 8 (max,sum) partials -> (max, 1/sum)
__global__ __launch_bounds__(256)
void combine_kernel(const float* __restrict__ pm, const float* __restrict__ ps,
                    float* __restrict__ omax, float* __restrict__ oinv)
{
    int idx = blockIdx.x * 256 + threadIdx.x;   // 16384
    const float* m8 = pm + (size_t)idx * 8;
    const float* s8 = ps + (size_t)idx * 8;
    float m = -1e30f;
#pragma unroll
    for (int j = 0; j < 8; j++) m = fmaxf(m, m8[j]);
    float s = 0.f;
#pragma unroll
    for (int j = 0; j < 8; j++) s += s8[j] * __expf(m8[j] - m);
    omax[idx] = m;
    oinv[idx] = 1.0f / s;
}

// fused: A1 = rowsoftmax(S) split (row-major) AND A2T = colsoftmax(S)^T split
__global__ __launch_bounds__(256)
void softmax_apply(const float* __restrict__ S,
                   const float* __restrict__ rmax, const float* __restrict__ rinv,
                   const float* __restrict__ cmax, const float* __restrict__ cinv,
                   __nv_bfloat16* __restrict__ A1h, __nv_bfloat16* __restrict__ A1l,
                   __nv_bfloat16* __restrict__ A2h, __nv_bfloat16* __restrict__ A2l)
{
    __shared__ float tl[32][33];
    const int z = blockIdx.z;
    const int bx = blockIdx.x * 32, by = blockIdx.y * 32;
    const int x = threadIdx.x, y = threadIdx.y;
    const float* Sp = S + (size_t)z * MATS;
#pragma unroll
    for (int i = 0; i < 4; i++) {
        int row = by + y + 8 * i;
        float v = Sp[(size_t)row * DIMN + bx + x];
        tl[y + 8 * i][x] = v;
        float val = __expf(v - rmax[z * DIMN + row]) * rinv[z * DIMN + row];
        __nv_bfloat16 hh, ll;
        bsplit(val, hh, ll);
        size_t o = (size_t)z * MATS + (size_t)row * DIMN + bx + x;
        A1h[o] = hh; A1l[o] = ll;
    }
    __syncthreads();
#pragma unroll
    for (int i = 0; i < 4; i++) {
        int cI = bx + y + 8 * i;
        float v = tl[x][y + 8 * i];
        float val = __expf(v - cmax[z * DIMN + cI]) * cinv[z * DIMN + cI];
        __nv_bfloat16 hh, ll;
        bsplit(val, hh, ll);
        size_t o = (size_t)z * MATS + (size_t)cI * DIMN + by + x;
        A2h[o] = hh; A2l[o] = ll;
    }
}

// transpose + split: in[z][r][c] -> out[z][c][r]
__global__ __launch_bounds__(256)
void tsplit_kernel(const float* __restrict__ in, __nv_bfloat16* __restrict__ h,
                   __nv_bfloat16* __restrict__ l)
{
    __shared__ float tl[32][33];
    const int z = blockIdx.z;
    const float* src = in + (size_t)z * MATS;
    const int bx = blockIdx.x * 32, by = blockIdx.y * 32;
    const int x = threadIdx.x, y = threadIdx.y;
#pragma unroll
    for (int i = 0; i < 4; i++)
        tl[y + 8 * i][x] = src[(size_t)(by + y + 8 * i) * DIMN + bx + x];
    __syncthreads();
#pragma unroll
    for (int i = 0; i < 4; i++) {
        int cI = bx + y + 8 * i;
        float v = tl[x][y + 8 * i];
        __nv_bfloat16 hh, ll;
        bsplit(v, hh, ll);
        size_t o = (size_t)z * MATS + (size_t)cI * DIMN + by + x;
        h[o] = hh; l[o] = ll;
    }
}

// ---------------- launcher ----------------
extern "C" void kernel_launch(void* const* d_in, const int* in_sizes, int n_in,
                              void* d_out, int out_size)
{
    const float* a1 = (const float*)d_in[0];
    const float* a2 = (const float*)d_in[1];
    const float* Gw = (const float*)d_in[2];
    const float* Gb = (const float*)d_in[3];
    float* M1 = (float*)d_out;
    float* M2 = M1 + TOT;

    __nv_bfloat16 *a1h, *a1l, *a2h, *a2l, *gwh, *gwl, *a2ph, *a2pl;
    __nv_bfloat16 *A1h, *A1l, *A2h, *A2l, *a2Th, *a2Tl, *a1Th, *a1Tl;
    float *S, *rmax, *rinv, *cmax, *cinv, *rpm, *rps, *cpm, *cps;
    cudaGetSymbolAddress((void**)&a1h, g_a1h);   cudaGetSymbolAddress((void**)&a1l, g_a1l);
    cudaGetSymbolAddress((void**)&a2h, g_a2h);   cudaGetSymbolAddress((void**)&a2l, g_a2l);
    cudaGetSymbolAddress((void**)&gwh, g_gwh);   cudaGetSymbolAddress((void**)&gwl, g_gwl);
    cudaGetSymbolAddress((void**)&a2ph, g_a2ph); cudaGetSymbolAddress((void**)&a2pl, g_a2pl);
    cudaGetSymbolAddress((void**)&A1h, g_A1h);   cudaGetSymbolAddress((void**)&A1l, g_A1l);
    cudaGetSymbolAddress((void**)&A2h, g_A2h);   cudaGetSymbolAddress((void**)&A2l, g_A2l);
    cudaGetSymbolAddress((void**)&a2Th, g_a2Th); cudaGetSymbolAddress((void**)&a2Tl, g_a2Tl);
    cudaGetSymbolAddress((void**)&a1Th, g_a1Th); cudaGetSymbolAddress((void**)&a1Tl, g_a1Tl);
    cudaGetSymbolAddress((void**)&S, g_S);
    cudaGetSymbolAddress((void**)&rmax, g_rmax); cudaGetSymbolAddress((void**)&rinv, g_rinv);
    cudaGetSymbolAddress((void**)&cmax, g_cmax); cudaGetSymbolAddress((void**)&cinv, g_cinv);
    cudaGetSymbolAddress((void**)&rpm, g_rpm);   cudaGetSymbolAddress((void**)&rps, g_rps);
    cudaGetSymbolAddress((void**)&cpm, g_cpm);   cudaGetSymbolAddress((void**)&cps, g_cps);

    cudaFuncSetAttribute(gemm_a2p,  cudaFuncAttributeMaxDynamicSharedMemorySize, SMEM_TOT);
    cudaFuncSetAttribute(gemm_S,    cudaFuncAttributeMaxDynamicSharedMemorySize, SMEM_TOT);
    cudaFuncSetAttribute(gemm_dual, cudaFuncAttributeMaxDynamicSharedMemorySize, SMEM_TOT);

    // splits
    split_kernel<<<16384, 256>>>(a1, a1h, a1l);
    split_kernel<<<16384, 256>>>(a2, a2h, a2l);
    split_kernel<<<1024, 256>>>(Gw, gwh, gwl);

    // transposed operand splits (independent of GEMMs)
    tsplit_kernel<<<dim3(32, 32, NB), dim3(32, 8)>>>(a2, a2Th, a2Tl);
    tsplit_kernel<<<dim3(32, 32, NB), dim3(32, 8)>>>(a1, a1Th, a1Tl);

    // 1) a2p = a2 @ Gw^T + Gb  -> split bf16 pair
    gemm_a2p<<<dim3(8, 128, 1), 256, SMEM_TOT>>>(a2h, a2l, gwh, gwl, a2ph, a2pl, Gb);

    // 2) S[n] = a1[n] @ a2p[n]^T + fused softmax partials
    gemm_S<<<dim3(8, 8, NB), 256, SMEM_TOT>>>(a1h, a1l, a2ph, a2pl, S, rpm, rps, cpm, cps);

    // 3) combine partials -> (max, 1/sum)
    combine_kernel<<<64, 256>>>(rpm, rps, rmax, rinv);
    combine_kernel<<<64, 256>>>(cpm, cps, cmax, cinv);

    // 4) fused softmax apply: A1 (row-major) + A2^T
    softmax_apply<<<dim3(32, 32, NB), dim3(32, 8)>>>(
        S, rmax, rinv, cmax, cinv, A1h, A1l, A2h, A2l);

    // 5) M1 = A1 @ a2  and  M2 = A2^T @ a1 in one launch
    gemm_dual<<<dim3(8, 8, 2 * NB), 256, SMEM_TOT>>>(
        A1h, A1l, a2Th, a2Tl, M1,
        A2h, A2l, a1Th, a1Tl, M2);
}